// round 14
// baseline (speedup 1.0000x reference)
#include <cuda_runtime.h>
#include <cuda_fp16.h>
#include <math.h>
#include <stdint.h>
typedef __half hlf;

#define EPSBN 1e-5f
#define B_    64
#define CIN   1024
#define P_    512
#define COUT  2048
#define NSP   256
#define HEADS 4
#define DH    128

// ---------------- scratch ----------------
__device__ __align__(16) hlf g_xt  [16777216];  // xT[b][n][cin]
__device__ __align__(16) hlf g_w1  [524288];
__device__ __align__(16) hlf g_wqkv[786432];    // [wq;wk;wv(BN2-scaled)] [1536][512]
__device__ __align__(16) hlf g_w3  [1048576];
__device__ __align__(16) hlf g_wsc [2097152];
__device__ __align__(16) hlf g_o1  [8388608];   // out1[b][n][p]
__device__ __align__(16) hlf g_qkv [25165824];  // qkv[b][n][1536]
__device__ __align__(16) hlf g_ao  [8388608];   // attout[b][n][p]
__device__ __align__(16) hlf g_pos [131072];    // posT[h][n][d]
__device__ __align__(16) float d_t1[P_], d_tfin[COUT], d_qkvb[1536];

// ---------------- helpers ----------------
__device__ __forceinline__ uint32_t su32(const void* p){uint32_t a;asm("{ .reg .u64 t; cvta.to.shared.u64 t, %1; cvt.u32.u64 %0, t; }":"=r"(a):"l"(p));return a;}
__device__ __forceinline__ void cp16(uint32_t d, const void* s){asm volatile("cp.async.cg.shared.global [%0], [%1], 16;"::"r"(d),"l"(s));}
__device__ __forceinline__ uint32_t pk(hlf a, hlf b){return (uint32_t)__half_as_ushort(a)|((uint32_t)__half_as_ushort(b)<<16);}
__device__ __forceinline__ void mma16816(float* c, const uint32_t* a, const uint32_t* b){
    asm volatile("mma.sync.aligned.m16n8k16.row.col.f32.f16.f16.f32 "
        "{%0,%1,%2,%3},{%4,%5,%6,%7},{%8,%9},{%0,%1,%2,%3};"
        : "+f"(c[0]), "+f"(c[1]), "+f"(c[2]), "+f"(c[3])
        : "r"(a[0]), "r"(a[1]), "r"(a[2]), "r"(a[3]), "r"(b[0]), "r"(b[1]));
}
#define LDM4(r, a) asm volatile("ldmatrix.sync.aligned.m8n8.x4.shared.b16 {%0,%1,%2,%3}, [%4];" \
    : "=r"((r)[0]),"=r"((r)[1]),"=r"((r)[2]),"=r"((r)[3]) : "r"(a))
#define LDM4T(r, a) asm volatile("ldmatrix.sync.aligned.m8n8.x4.trans.shared.b16 {%0,%1,%2,%3}, [%4];" \
    : "=r"((r)[0]),"=r"((r)[1]),"=r"((r)[2]),"=r"((r)[3]) : "r"(a))
template<int N> __device__ __forceinline__ void cpwait(){
    asm volatile("cp.async.wait_group %0;"::"n"(N):"memory");
}

// ---------------- tensor-core GEMM: BM=128, BN=256, BK=32, warp tile 64x64 ----------------
// 8 warps = 2(M) x 4(N). 4-buf single-sync pipeline, 1 CTA/SM.
#define PLANEA 10240
#define PLANEB 20480
#define BUFSZ  30720
#define SMEMSZ 122880

template<bool BIASROW, bool RELU, bool HAS2, bool OUTHF>
__global__ void __launch_bounds__(256,1) tc(
  const hlf* __restrict__ A1, long aso1, long asi1, int adiv1, int lda1, int K1,
  const hlf* __restrict__ B1, long bso1, long bsi1, int bdiv1, int ldb1,
  const hlf* __restrict__ A2, long aso2, long asi2, int adiv2, int lda2, int K2,
  const hlf* __restrict__ B2, long bso2, long bsi2, int bdiv2, int ldb2,
  void* __restrict__ C, long cso, long csi, int cdiv, int ldc,
  const float* __restrict__ bias)
{
    extern __shared__ char sm[];
    const uint32_t sbase = su32(sm);
    const int tid = threadIdx.x;
    const int z = blockIdx.z, m0 = blockIdx.y*128, n0 = blockIdx.x*256;
    const int lane = tid&31, w = tid>>5;
    const int wm = w>>2, wn = w&3;                 // 2 x 4 warp grid, warp tile 64x64
    const int qr = lane>>2, qk = lane&3;

    const uint32_t a_off = (uint32_t)(wm*64 + (lane&15))*80 + (uint32_t)(lane>>4)*16;
    const uint32_t b_off = (uint32_t)(wn*64 + (lane&7) + ((lane>>4)<<3))*80 + (uint32_t)((lane>>3)&1)*16;

    const hlf* pA1 = A1 + (long)(z/adiv1)*aso1 + (long)(z%adiv1)*asi1;
    const hlf* pB1 = B1 + (long)(z/bdiv1)*bso1 + (long)(z%bdiv1)*bsi1;
    const hlf* pA2 = HAS2 ? A2 + (long)(z/adiv2)*aso2 + (long)(z%adiv2)*asi2 : nullptr;
    const hlf* pB2 = HAS2 ? B2 + (long)(z/bdiv2)*bso2 + (long)(z%bdiv2)*bsi2 : nullptr;
    const int nst1 = K1/32, nst = nst1 + (HAS2 ? K2/32 : 0);

    float acc[4][8][4];
#pragma unroll
    for(int i=0;i<4;++i)
#pragma unroll
        for(int j=0;j<8;++j)
#pragma unroll
            for(int q=0;q<4;++q) acc[i][j][q]=0.0f;

    auto ld=[&](int c){
        const hlf *pa,*pb; int la,lb,k0;
        if(!HAS2 || c<nst1){ pa=pA1; pb=pB1; la=lda1; lb=ldb1; k0=c*32; }
        else               { pa=pA2; pb=pB2; la=lda2; lb=ldb2; k0=(c-nst1)*32; }
        uint32_t sb = sbase + (uint32_t)(c&3)*BUFSZ;
        // A: 128 rows x 32k
#pragma unroll
        for(int it=0;it<2;++it){
            int ch=tid+it*256, r=ch>>2, q=ch&3;
            cp16(sb + (uint32_t)r*80 + q*16, pa + (long)(m0+r)*la + k0 + q*8);
        }
        // B: 256 rows x 32k
#pragma unroll
        for(int it=0;it<4;++it){
            int ch=tid+it*256, r=ch>>2, q=ch&3;
            cp16(sb + PLANEA + (uint32_t)r*80 + q*16, pb + (long)(n0+r)*lb + k0 + q*8);
        }
        asm volatile("cp.async.commit_group;":::"memory");
    };

    auto compute=[&](int buf){
        const uint32_t base = sbase + (uint32_t)buf*BUFSZ;
#pragma unroll
        for(int s=0;s<2;++s){
            uint32_t ah[4][4];
#pragma unroll
            for(int mi=0;mi<4;++mi) LDM4(ah[mi], base + a_off + mi*1280 + s*32);
#pragma unroll
            for(int nq=0;nq<4;++nq){
                uint32_t bh[4];
                LDM4(bh, base + PLANEA + b_off + nq*1280 + s*32);
#pragma unroll
                for(int hf=0;hf<2;++hf){
                    int ni = nq*2 + hf;
#pragma unroll
                    for(int mi=0;mi<4;++mi) mma16816(acc[mi][ni], ah[mi], bh + hf*2);
                }
            }
        }
    };

    ld(0);
    if(nst>1) ld(1);
    if(nst>2) ld(2);
    for(int c=0;c<nst;++c){
        int out = nst - c;
        if(out >= 3)    cpwait<2>();
        else if(out==2) cpwait<1>();
        else            cpwait<0>();
        __syncthreads();
        if(c+3<nst) ld(c+3);          // overwrites buffer (c-1)&3: safe post-barrier
        compute(c&3);
    }

    long cz = (long)(z/cdiv)*cso + (long)(z%cdiv)*csi;
#pragma unroll
    for(int mi=0;mi<4;++mi){
#pragma unroll
        for(int hf=0;hf<2;++hf){
            int row = m0 + wm*64 + mi*16 + qr + hf*8;
            float tr = (BIASROW && bias) ? __ldg(bias+row) : 0.0f;
#pragma unroll
            for(int ni=0;ni<8;++ni){
                int col = n0 + wn*64 + ni*8 + qk*2;
                float v0 = acc[mi][ni][hf*2], v1 = acc[mi][ni][hf*2+1];
                if(BIASROW){ v0 += tr; v1 += tr; }
                else if(bias){ v0 += __ldg(bias+col); v1 += __ldg(bias+col+1); }
                if(RELU){ v0 = fmaxf(v0,0.0f); v1 = fmaxf(v1,0.0f); }
                if(OUTHF){
                    hlf* Cb = (hlf*)C + cz + (long)row*ldc + col;
                    *(uint32_t*)Cb = pk(__float2half(v0), __float2half(v1));
                } else {
                    float2 f = {v0, v1};
                    *(float2*)((float*)C + cz + (long)row*ldc + col) = f;
                }
            }
        }
    }
}

// ---------------- fused attention: logits + softmax + attn·V ----------------
#define FA_OV 61440
#define FA_OP 131072
#define FA_OR 198656
#define FA_SMEM 199680

__global__ void __launch_bounds__(256) fattn(
  const hlf* __restrict__ QKV, const hlf* __restrict__ POS,
  hlf* __restrict__ AO)
{
    extern __shared__ char sm[];
    const uint32_t sbase = su32(sm);
    const int tid=threadIdx.x, lane=tid&31, w=tid>>5, wm=w>>1, wn=w&1;
    const int qr=lane>>2, qk=lane&3;
    const int m0 = blockIdx.x*128;
    const int z = blockIdx.y, b = z>>2, h = z&3;

    const hlf* pq = QKV + (long)b*393216;
    const hlf* pkk = pq + 512;
    const hlf* pv  = pq + 1024 + h*128;
    const hlf* pp = POS + (long)h*32768;

    const uint32_t a_off = (uint32_t)(wm*32+(lane&15))*80 + (uint32_t)(lane>>4)*16;
    const uint32_t b_off = (uint32_t)((lane&7)+((lane>>4)<<3))*80 + (uint32_t)((lane>>3)&1)*16;

    auto ldA=[&](int c){
        uint32_t sb = sbase + (uint32_t)(c&1)*30720;
        const hlf *pa, *pb; int la;
        if(c<4){ pa = pq + (long)m0*1536 + h*128 + c*32; la=1536; pb = pkk + h*128 + c*32; }
        else   { pa = pp + (long)m0*128 + (c-4)*32;      la=128;  pb = pq  + h*128 + (c-4)*32; }
#pragma unroll
        for(int it=0;it<2;++it){
            int ch=tid+it*256, r=ch>>2, q2=ch&3;
            cp16(sb + (uint32_t)r*80 + q2*16, pa + (long)r*la + q2*8);
        }
#pragma unroll
        for(int it=0;it<4;++it){
            int ch=tid+it*256, r=ch>>2, q2=ch&3;
            cp16(sb + 10240 + (uint32_t)r*80 + q2*16, pb + (long)r*1536 + q2*8);
        }
        asm volatile("cp.async.commit_group;":::"memory");
    };

#pragma unroll
    for(int it=0;it<16;++it){
        int ch = tid + it*256;
        int r = ch>>4, cq = ch&15;
        cp16(sbase + FA_OV + (uint32_t)r*272 + cq*16, pv + (long)r*1536 + cq*8);
    }
    ldA(0); ldA(1);

    float acc[2][16][4];
#pragma unroll
    for(int i=0;i<2;++i)
#pragma unroll
        for(int j=0;j<16;++j)
#pragma unroll
            for(int q=0;q<4;++q) acc[i][j][q]=0.0f;

    for(int c=0;c<8;++c){
        if(c<7) cpwait<1>(); else cpwait<0>();
        __syncthreads();
        const uint32_t base = sbase + (uint32_t)(c&1)*30720;
#pragma unroll
        for(int s=0;s<2;++s){
            uint32_t ah[2][4];
#pragma unroll
            for(int mi=0;mi<2;++mi) LDM4(ah[mi], base + a_off + mi*1280 + s*32);
#pragma unroll
            for(int nq=0;nq<8;++nq){
                uint32_t bh[4];
                LDM4(bh, base + 10240 + (uint32_t)wn*10240 + nq*1280 + b_off + s*32);
#pragma unroll
                for(int hf=0;hf<2;++hf){
                    int ni = nq*2+hf;
#pragma unroll
                    for(int mi=0;mi<2;++mi) mma16816(acc[mi][ni], ah[mi], bh+hf*2);
                }
            }
        }
        __syncthreads();
        if(c+2<8) ldA(c+2);
    }

    float* red = (float*)(sm + FA_OR);
    float mxv[2][2], inv[2][2];
#pragma unroll
    for(int mi=0;mi<2;++mi)
#pragma unroll
    for(int hf=0;hf<2;++hf){
        float m = -1e30f;
#pragma unroll
        for(int ni=0;ni<16;++ni){ m=fmaxf(m,acc[mi][ni][hf*2]); m=fmaxf(m,acc[mi][ni][hf*2+1]); }
        m = fmaxf(m, __shfl_xor_sync(~0u,m,1));
        m = fmaxf(m, __shfl_xor_sync(~0u,m,2));
        if(qk==0) red[(wm*32+mi*16+hf*8+qr)*2+wn] = m;
    }
    __syncthreads();
#pragma unroll
    for(int mi=0;mi<2;++mi)
#pragma unroll
    for(int hf=0;hf<2;++hf){
        int r = wm*32+mi*16+hf*8+qr;
        mxv[mi][hf] = fmaxf(red[r*2], red[r*2+1]);
    }
    __syncthreads();
#pragma unroll
    for(int mi=0;mi<2;++mi)
#pragma unroll
    for(int hf=0;hf<2;++hf){
        float s = 0.0f;
#pragma unroll
        for(int ni=0;ni<16;++ni){
            float e0=__expf(acc[mi][ni][hf*2]  -mxv[mi][hf]);
            float e1=__expf(acc[mi][ni][hf*2+1]-mxv[mi][hf]);
            acc[mi][ni][hf*2]=e0; acc[mi][ni][hf*2+1]=e1; s+=e0+e1;
        }
        s += __shfl_xor_sync(~0u,s,1);
        s += __shfl_xor_sync(~0u,s,2);
        if(qk==0) red[(wm*32+mi*16+hf*8+qr)*2+wn] = s;
    }
    __syncthreads();
#pragma unroll
    for(int mi=0;mi<2;++mi)
#pragma unroll
    for(int hf=0;hf<2;++hf){
        int r = wm*32+mi*16+hf*8+qr;
        inv[mi][hf] = 1.0f/(red[r*2]+red[r*2+1]);
    }
#pragma unroll
    for(int mi=0;mi<2;++mi)
#pragma unroll
    for(int hf=0;hf<2;++hf){
        int r = wm*32+mi*16+hf*8+qr;
#pragma unroll
        for(int ni=0;ni<16;++ni){
            int col = wn*128+ni*8+qk*2;
            uint32_t p2 = pk(__float2half(acc[mi][ni][hf*2]  *inv[mi][hf]),
                             __float2half(acc[mi][ni][hf*2+1]*inv[mi][hf]));
            *(uint32_t*)(sm + FA_OP + (uint32_t)r*528 + col*2) = p2;
        }
    }
    __syncthreads();

    float ao_acc[2][8][4];
#pragma unroll
    for(int i=0;i<2;++i)
#pragma unroll
        for(int j=0;j<8;++j)
#pragma unroll
            for(int q=0;q<4;++q) ao_acc[i][j][q]=0.0f;

    const uint32_t pa2 = (uint32_t)(wm*32+(lane&15))*528 + (uint32_t)(lane>>4)*16;
    const uint32_t vb2 = (uint32_t)(lane&15)*272 + (uint32_t)(lane>>4)*16 + (uint32_t)wn*128;
#pragma unroll 2
    for(int ks=0;ks<16;++ks){
        uint32_t ap[2][4];
#pragma unroll
        for(int mi=0;mi<2;++mi) LDM4(ap[mi], sbase + FA_OP + pa2 + mi*(16*528) + ks*32);
#pragma unroll
        for(int dq=0;dq<4;++dq){
            uint32_t bv[4];
            LDM4T(bv, sbase + FA_OV + vb2 + ks*(16*272) + dq*32);
#pragma unroll
            for(int hf=0;hf<2;++hf){
                int ni = dq*2+hf;
#pragma unroll
                for(int mi=0;mi<2;++mi) mma16816(ao_acc[mi][ni], ap[mi], bv+hf*2);
            }
        }
    }

    hlf* po = AO + (long)b*131072 + h*128;
#pragma unroll
    for(int mi=0;mi<2;++mi)
#pragma unroll
    for(int hf=0;hf<2;++hf){
        int row = m0 + wm*32+mi*16+hf*8+qr;
#pragma unroll
        for(int ni=0;ni<8;++ni){
            int d = wn*64+ni*8+qk*2;
            float v0=fmaxf(ao_acc[mi][ni][hf*2],0.f), v1=fmaxf(ao_acc[mi][ni][hf*2+1],0.f);
            *(uint32_t*)(po + (long)row*512 + d) = pk(__float2half(v0), __float2half(v1));
        }
    }
}

// ---------------- fused prep ----------------
__global__ void k_prep(const float* c1w, const float* b1g, const float* b1b, const float* b1m, const float* b1v,
                       const float* qw, const float* qbv, const float* kw, const float* kbv,
                       const float* vw, const float* vbv,
                       const float* b2g, const float* b2b, const float* b2m, const float* b2v,
                       const float* c3w, const float* b3g, const float* b3b, const float* b3m, const float* b3v,
                       const float* scw, const float* scb,
                       const float* sg, const float* sb, const float* smn, const float* sv,
                       const float* rh, const float* rw,
                       hlf* w1, hlf* wqkv, hlf* w3, hlf* wsc, hlf* pos){
    int blk = blockIdx.x, t = threadIdx.x;
    if(blk < 2048){
        int i = blk*256+t;
        int o = i>>10;
        w1[i] = __float2half(c1w[i] * (b1g[o]*rsqrtf(b1v[o]+EPSBN)));
    } else if(blk < 3072){
        int i = (blk-2048)*256+t;
        wqkv[i] = __float2half(qw[i]);
    } else if(blk < 4096){
        int i = (blk-3072)*256+t;
        wqkv[262144+i] = __float2half(kw[i]);
    } else if(blk < 5120){
        int i = (blk-4096)*256+t;
        int o = i>>9;
        wqkv[524288+i] = __float2half(vw[i] * (b2g[o]*rsqrtf(b2v[o]+EPSBN)));
    } else if(blk < 9216){
        int i = (blk-5120)*256+t;
        int o = i>>9;
        w3[i] = __float2half(c3w[i] * (b3g[o]*rsqrtf(b3v[o]+EPSBN)));
    } else if(blk < 17408){
        int i = (blk-9216)*256+t;
        int o = i>>10;
        wsc[i] = __float2half(scw[i] * (sg[o]*rsqrtf(sv[o]+EPSBN)));
    } else if(blk < 17920){
        int i = (blk-17408)*256+t;
        int hd = ((i>>15)<<7) + (i&127), n = (i>>7)&255;
        pos[i] = __float2half(rh[hd*16+(n&15)] + rw[hd*16+(n>>4)]);
    } else {
        int i = (blk-17920)*256+t;
        if(i<P_){
            float s1=b1g[i]*rsqrtf(b1v[i]+EPSBN); d_t1[i]=b1b[i]-b1m[i]*s1;
            float s2=b2g[i]*rsqrtf(b2v[i]+EPSBN);
            d_qkvb[i]=qbv[i];
            d_qkvb[i+512]=kbv[i];
            d_qkvb[i+1024]=fmaf(vbv[i],s2,b2b[i]-b2m[i]*s2);
        }
        if(i<COUT){
            float s3=b3g[i]*rsqrtf(b3v[i]+EPSBN);
            float ss=sg[i]*rsqrtf(sv[i]+EPSBN);
            d_tfin[i]=(b3b[i]-b3m[i]*s3) + fmaf(scb[i]-smn[i],ss,sb[i]);
        }
    }
}
__global__ void k_xt(const float* __restrict__ x, hlf* __restrict__ o){
    __shared__ float t[32][33];
    int c0=blockIdx.x*32, nn0=blockIdx.y*32, b=blockIdx.z, tx=threadIdx.x, ty=threadIdx.y;
#pragma unroll
    for(int i=0;i<4;++i) t[ty+i*8][tx] = x[((long)b*1024 + c0+ty+i*8)*256 + nn0+tx];
    __syncthreads();
    hlf* ob = o + (long)b*262144;
#pragma unroll
    for(int i=0;i<4;++i)
        ob[(long)(nn0+ty+i*8)*1024 + c0+tx] = __float2half(t[tx][ty+i*8]);
}

// ---------------- launch ----------------
extern "C" void kernel_launch(void* const* d_in, const int* in_sizes, int n_in,
                              void* d_out, int out_size) {
    const float *x=(const float*)d_in[0], *c1w=(const float*)d_in[1];
    const float *b1g=(const float*)d_in[2],*b1b=(const float*)d_in[3],*b1m=(const float*)d_in[4],*b1v=(const float*)d_in[5];
    const float *qw=(const float*)d_in[6],*qbv=(const float*)d_in[7],*kw=(const float*)d_in[8],*kbv=(const float*)d_in[9];
    const float *vw=(const float*)d_in[10],*vbv=(const float*)d_in[11],*rh=(const float*)d_in[12],*rwv=(const float*)d_in[13];
    const float *b2g=(const float*)d_in[14],*b2b=(const float*)d_in[15],*b2m=(const float*)d_in[16],*b2v=(const float*)d_in[17];
    const float *c3w=(const float*)d_in[18];
    const float *b3g=(const float*)d_in[19],*b3b=(const float*)d_in[20],*b3m=(const float*)d_in[21],*b3v=(const float*)d_in[22];
    const float *scw=(const float*)d_in[23],*scb=(const float*)d_in[24];
    const float *sg=(const float*)d_in[25],*sb=(const float*)d_in[26],*smn=(const float*)d_in[27],*sv=(const float*)d_in[28];

    hlf *xt,*w1,*wqkv,*w3,*wsc,*o1,*qkv,*ao,*pos;
    float *t1,*tf,*qkvb;
    cudaGetSymbolAddress((void**)&xt, g_xt);    cudaGetSymbolAddress((void**)&w1, g_w1);
    cudaGetSymbolAddress((void**)&wqkv,g_wqkv); cudaGetSymbolAddress((void**)&w3, g_w3);
    cudaGetSymbolAddress((void**)&wsc,g_wsc);   cudaGetSymbolAddress((void**)&o1, g_o1);
    cudaGetSymbolAddress((void**)&qkv,g_qkv);   cudaGetSymbolAddress((void**)&ao, g_ao);
    cudaGetSymbolAddress((void**)&pos,g_pos);
    cudaGetSymbolAddress((void**)&t1, d_t1);    cudaGetSymbolAddress((void**)&tf, d_tfin);
    cudaGetSymbolAddress((void**)&qkvb, d_qkvb);

    cudaFuncSetAttribute(tc<false,true ,false,true >, cudaFuncAttributeMaxDynamicSharedMemorySize, SMEMSZ);
    cudaFuncSetAttribute(tc<false,false,false,true >, cudaFuncAttributeMaxDynamicSharedMemorySize, SMEMSZ);
    cudaFuncSetAttribute(tc<true ,true ,true ,false>, cudaFuncAttributeMaxDynamicSharedMemorySize, SMEMSZ);
    cudaFuncSetAttribute(fattn, cudaFuncAttributeMaxDynamicSharedMemorySize, FA_SMEM);

    // prep (2 launches)
    k_prep<<<17928,256>>>(c1w,b1g,b1b,b1m,b1v, qw,qbv,kw,kbv, vw,vbv,
                          b2g,b2b,b2m,b2v, c3w,b3g,b3b,b3m,b3v, scw,scb,
                          sg,sb,smn,sv, rh,rwv, w1,wqkv,w3,wsc,pos);
    k_xt<<<dim3(32,8,64),dim3(32,8)>>>(x, xt);

    // 1) out1[b][n][p] = xT·w1 + t1[col], ReLU
    tc<false,true,false,true><<<dim3(2,2,64),256,SMEMSZ>>>(
        xt,262144,0,1,1024,1024,  w1,0,0,1,1024,
        nullptr,0,0,1,0,0, nullptr,0,0,1,0,
        o1,131072,0,1,512, t1);
    // 2) qkv[b][n][0..1535] = o1·[wq;wk;wv'] + qkvb[col]
    tc<false,false,false,true><<<dim3(6,2,64),256,SMEMSZ>>>(
        o1,131072,0,1,512,512,  wqkv,0,0,1,512,
        nullptr,0,0,1,0,0, nullptr,0,0,1,0,
        qkv,393216,0,1,1536, qkvb);
    // 3-5) fused attention
    fattn<<<dim3(2,256),256,FA_SMEM>>>(qkv, pos, ao);
    // 6) out[b][cout][n] = w3·attout + wsc·xT + tfin[row], ReLU (two-phase)
    tc<true,true,true,false><<<dim3(1,16,64),256,SMEMSZ>>>(
        w3,0,0,1,512,512,  ao,131072,0,1,512,
        wsc,0,0,1,1024,1024,  xt,262144,0,1,1024,
        d_out,524288,0,1,256, tf);
}

// round 15
// speedup vs baseline: 1.1566x; 1.1566x over previous
#include <cuda_runtime.h>
#include <cuda_fp16.h>
#include <math.h>
#include <stdint.h>
typedef __half hlf;

#define EPSBN 1e-5f
#define B_    64
#define CIN   1024
#define P_    512
#define COUT  2048
#define NSP   256
#define HEADS 4
#define DH    128

// ---------------- scratch ----------------
__device__ __align__(16) hlf g_xt  [16777216];  // xT[b][n][cin]
__device__ __align__(16) hlf g_w1  [524288];
__device__ __align__(16) hlf g_wqkv[786432];    // [wq;wk;wv(BN2-scaled)] [1536][512]
__device__ __align__(16) hlf g_w3  [1048576];
__device__ __align__(16) hlf g_wsc [2097152];
__device__ __align__(16) hlf g_o1  [8388608];   // out1[b][n][p]
__device__ __align__(16) hlf g_qkv [25165824];  // qkv[b][n][1536]
__device__ __align__(16) hlf g_ao  [8388608];   // attout[b][n][p]
__device__ __align__(16) hlf g_pos [131072];    // posT[h][n][d]
__device__ __align__(16) float d_t1[P_], d_tfin[COUT], d_qkvb[1536];

// ---------------- helpers ----------------
__device__ __forceinline__ uint32_t su32(const void* p){uint32_t a;asm("{ .reg .u64 t; cvta.to.shared.u64 t, %1; cvt.u32.u64 %0, t; }":"=r"(a):"l"(p));return a;}
__device__ __forceinline__ void cp16(uint32_t d, const void* s){asm volatile("cp.async.cg.shared.global [%0], [%1], 16;"::"r"(d),"l"(s));}
__device__ __forceinline__ uint32_t pk(hlf a, hlf b){return (uint32_t)__half_as_ushort(a)|((uint32_t)__half_as_ushort(b)<<16);}
__device__ __forceinline__ void mma16816(float* c, const uint32_t* a, const uint32_t* b){
    asm volatile("mma.sync.aligned.m16n8k16.row.col.f32.f16.f16.f32 "
        "{%0,%1,%2,%3},{%4,%5,%6,%7},{%8,%9},{%0,%1,%2,%3};"
        : "+f"(c[0]), "+f"(c[1]), "+f"(c[2]), "+f"(c[3])
        : "r"(a[0]), "r"(a[1]), "r"(a[2]), "r"(a[3]), "r"(b[0]), "r"(b[1]));
}
#define LDM4(r, a) asm volatile("ldmatrix.sync.aligned.m8n8.x4.shared.b16 {%0,%1,%2,%3}, [%4];" \
    : "=r"((r)[0]),"=r"((r)[1]),"=r"((r)[2]),"=r"((r)[3]) : "r"(a))
#define LDM4T(r, a) asm volatile("ldmatrix.sync.aligned.m8n8.x4.trans.shared.b16 {%0,%1,%2,%3}, [%4];" \
    : "=r"((r)[0]),"=r"((r)[1]),"=r"((r)[2]),"=r"((r)[3]) : "r"(a))
template<int N> __device__ __forceinline__ void cpwait(){
    asm volatile("cp.async.wait_group %0;"::"n"(N):"memory");
}

// ---------------- tensor-core GEMM: 128 threads, CTA tile 64x128, warp tile 32x64 ----------------
// 4 warps = 2(M) x 2(N). 3 buffers x {A 64x80B, B 128x80B} = 46 KB. 4 CTA/SM.
#define PLANEA 5120
#define BUFSZ  15360
#define SMEMSZ 46080

template<bool BIASROW, bool RELU, bool HAS2, bool OUTHF>
__global__ void __launch_bounds__(128,4) tc(
  const hlf* __restrict__ A1, long aso1, long asi1, int adiv1, int lda1, int K1,
  const hlf* __restrict__ B1, long bso1, long bsi1, int bdiv1, int ldb1,
  const hlf* __restrict__ A2, long aso2, long asi2, int adiv2, int lda2, int K2,
  const hlf* __restrict__ B2, long bso2, long bsi2, int bdiv2, int ldb2,
  void* __restrict__ C, long cso, long csi, int cdiv, int ldc,
  const float* __restrict__ bias)
{
    extern __shared__ char sm[];
    const uint32_t sbase = su32(sm);
    const int tid = threadIdx.x;
    const int z = blockIdx.z, m0 = blockIdx.y*64, n0 = blockIdx.x*128;
    const int lane = tid&31, w = tid>>5;
    const int wm = w>>1, wn = w&1;                 // 2 x 2 warp grid, warp tile 32x64
    const int qr = lane>>2, qk = lane&3;

    const uint32_t a_off = (uint32_t)(wm*32 + (lane&15))*80 + (uint32_t)(lane>>4)*16;
    const uint32_t b_off = (uint32_t)(wn*64 + (lane&7) + ((lane>>4)<<3))*80 + (uint32_t)((lane>>3)&1)*16;

    const hlf* pA1 = A1 + (long)(z/adiv1)*aso1 + (long)(z%adiv1)*asi1;
    const hlf* pB1 = B1 + (long)(z/bdiv1)*bso1 + (long)(z%bdiv1)*bsi1;
    const hlf* pA2 = HAS2 ? A2 + (long)(z/adiv2)*aso2 + (long)(z%adiv2)*asi2 : nullptr;
    const hlf* pB2 = HAS2 ? B2 + (long)(z/bdiv2)*bso2 + (long)(z%bdiv2)*bsi2 : nullptr;
    const int nst1 = K1/32, nst = nst1 + (HAS2 ? K2/32 : 0);

    float acc[2][8][4];
#pragma unroll
    for(int i=0;i<2;++i)
#pragma unroll
        for(int j=0;j<8;++j)
#pragma unroll
            for(int q=0;q<4;++q) acc[i][j][q]=0.0f;

    auto ld=[&](int c){
        const hlf *pa,*pb; int la,lb,k0;
        if(!HAS2 || c<nst1){ pa=pA1; pb=pB1; la=lda1; lb=ldb1; k0=c*32; }
        else               { pa=pA2; pb=pB2; la=lda2; lb=ldb2; k0=(c-nst1)*32; }
        uint32_t sb = sbase + (uint32_t)(c%3)*BUFSZ;
        // A: 64 rows x 32k
#pragma unroll
        for(int it=0;it<2;++it){
            int ch=tid+it*128, r=ch>>2, q=ch&3;
            cp16(sb + (uint32_t)r*80 + q*16, pa + (long)(m0+r)*la + k0 + q*8);
        }
        // B: 128 rows x 32k
#pragma unroll
        for(int it=0;it<4;++it){
            int ch=tid+it*128, r=ch>>2, q=ch&3;
            cp16(sb + PLANEA + (uint32_t)r*80 + q*16, pb + (long)(n0+r)*lb + k0 + q*8);
        }
        asm volatile("cp.async.commit_group;":::"memory");
    };

    auto compute=[&](int buf){
        const uint32_t base = sbase + (uint32_t)buf*BUFSZ;
#pragma unroll
        for(int s=0;s<2;++s){
            uint32_t ah[2][4];
#pragma unroll
            for(int mi=0;mi<2;++mi) LDM4(ah[mi], base + a_off + mi*1280 + s*32);
#pragma unroll
            for(int nq=0;nq<4;++nq){
                uint32_t bh[4];
                LDM4(bh, base + PLANEA + b_off + nq*1280 + s*32);
#pragma unroll
                for(int hf=0;hf<2;++hf){
                    int ni = nq*2 + hf;
#pragma unroll
                    for(int mi=0;mi<2;++mi) mma16816(acc[mi][ni], ah[mi], bh + hf*2);
                }
            }
        }
    };

    ld(0);
    if(nst>1) ld(1);
    for(int c=0;c<nst;++c){
        if(c+1<nst) cpwait<1>();
        else        cpwait<0>();
        __syncthreads();
        if(c+2<nst) ld(c+2);          // overwrites buffer (c-1)%3: computed last iter, safe post-barrier
        compute(c%3);
    }

    long cz = (long)(z/cdiv)*cso + (long)(z%cdiv)*csi;
#pragma unroll
    for(int mi=0;mi<2;++mi){
#pragma unroll
        for(int hf=0;hf<2;++hf){
            int row = m0 + wm*32 + mi*16 + qr + hf*8;
            float tr = (BIASROW && bias) ? __ldg(bias+row) : 0.0f;
#pragma unroll
            for(int ni=0;ni<8;++ni){
                int col = n0 + wn*64 + ni*8 + qk*2;
                float v0 = acc[mi][ni][hf*2], v1 = acc[mi][ni][hf*2+1];
                if(BIASROW){ v0 += tr; v1 += tr; }
                else if(bias){ v0 += __ldg(bias+col); v1 += __ldg(bias+col+1); }
                if(RELU){ v0 = fmaxf(v0,0.0f); v1 = fmaxf(v1,0.0f); }
                if(OUTHF){
                    hlf* Cb = (hlf*)C + cz + (long)row*ldc + col;
                    *(uint32_t*)Cb = pk(__float2half(v0), __float2half(v1));
                } else {
                    float2 f = {v0, v1};
                    *(float2*)((float*)C + cz + (long)row*ldc + col) = f;
                }
            }
        }
    }
}

// ---------------- fused attention: logits + softmax + attn·V ----------------
#define FA_OV 61440
#define FA_OP 131072
#define FA_OR 198656
#define FA_SMEM 199680

__global__ void __launch_bounds__(256) fattn(
  const hlf* __restrict__ QKV, const hlf* __restrict__ POS,
  hlf* __restrict__ AO)
{
    extern __shared__ char sm[];
    const uint32_t sbase = su32(sm);
    const int tid=threadIdx.x, lane=tid&31, w=tid>>5, wm=w>>1, wn=w&1;
    const int qr=lane>>2, qk=lane&3;
    const int m0 = blockIdx.x*128;
    const int z = blockIdx.y, b = z>>2, h = z&3;

    const hlf* pq = QKV + (long)b*393216;
    const hlf* pkk = pq + 512;
    const hlf* pv  = pq + 1024 + h*128;
    const hlf* pp = POS + (long)h*32768;

    const uint32_t a_off = (uint32_t)(wm*32+(lane&15))*80 + (uint32_t)(lane>>4)*16;
    const uint32_t b_off = (uint32_t)((lane&7)+((lane>>4)<<3))*80 + (uint32_t)((lane>>3)&1)*16;

    auto ldA=[&](int c){
        uint32_t sb = sbase + (uint32_t)(c&1)*30720;
        const hlf *pa, *pb; int la;
        if(c<4){ pa = pq + (long)m0*1536 + h*128 + c*32; la=1536; pb = pkk + h*128 + c*32; }
        else   { pa = pp + (long)m0*128 + (c-4)*32;      la=128;  pb = pq  + h*128 + (c-4)*32; }
#pragma unroll
        for(int it=0;it<2;++it){
            int ch=tid+it*256, r=ch>>2, q2=ch&3;
            cp16(sb + (uint32_t)r*80 + q2*16, pa + (long)r*la + q2*8);
        }
#pragma unroll
        for(int it=0;it<4;++it){
            int ch=tid+it*256, r=ch>>2, q2=ch&3;
            cp16(sb + 10240 + (uint32_t)r*80 + q2*16, pb + (long)r*1536 + q2*8);
        }
        asm volatile("cp.async.commit_group;":::"memory");
    };

#pragma unroll
    for(int it=0;it<16;++it){
        int ch = tid + it*256;
        int r = ch>>4, cq = ch&15;
        cp16(sbase + FA_OV + (uint32_t)r*272 + cq*16, pv + (long)r*1536 + cq*8);
    }
    ldA(0); ldA(1);

    float acc[2][16][4];
#pragma unroll
    for(int i=0;i<2;++i)
#pragma unroll
        for(int j=0;j<16;++j)
#pragma unroll
            for(int q=0;q<4;++q) acc[i][j][q]=0.0f;

    for(int c=0;c<8;++c){
        if(c<7) cpwait<1>(); else cpwait<0>();
        __syncthreads();
        const uint32_t base = sbase + (uint32_t)(c&1)*30720;
#pragma unroll
        for(int s=0;s<2;++s){
            uint32_t ah[2][4];
#pragma unroll
            for(int mi=0;mi<2;++mi) LDM4(ah[mi], base + a_off + mi*1280 + s*32);
#pragma unroll
            for(int nq=0;nq<8;++nq){
                uint32_t bh[4];
                LDM4(bh, base + 10240 + (uint32_t)wn*10240 + nq*1280 + b_off + s*32);
#pragma unroll
                for(int hf=0;hf<2;++hf){
                    int ni = nq*2+hf;
#pragma unroll
                    for(int mi=0;mi<2;++mi) mma16816(acc[mi][ni], ah[mi], bh+hf*2);
                }
            }
        }
        __syncthreads();
        if(c+2<8) ldA(c+2);
    }

    float* red = (float*)(sm + FA_OR);
    float mxv[2][2], inv[2][2];
#pragma unroll
    for(int mi=0;mi<2;++mi)
#pragma unroll
    for(int hf=0;hf<2;++hf){
        float m = -1e30f;
#pragma unroll
        for(int ni=0;ni<16;++ni){ m=fmaxf(m,acc[mi][ni][hf*2]); m=fmaxf(m,acc[mi][ni][hf*2+1]); }
        m = fmaxf(m, __shfl_xor_sync(~0u,m,1));
        m = fmaxf(m, __shfl_xor_sync(~0u,m,2));
        if(qk==0) red[(wm*32+mi*16+hf*8+qr)*2+wn] = m;
    }
    __syncthreads();
#pragma unroll
    for(int mi=0;mi<2;++mi)
#pragma unroll
    for(int hf=0;hf<2;++hf){
        int r = wm*32+mi*16+hf*8+qr;
        mxv[mi][hf] = fmaxf(red[r*2], red[r*2+1]);
    }
    __syncthreads();
#pragma unroll
    for(int mi=0;mi<2;++mi)
#pragma unroll
    for(int hf=0;hf<2;++hf){
        float s = 0.0f;
#pragma unroll
        for(int ni=0;ni<16;++ni){
            float e0=__expf(acc[mi][ni][hf*2]  -mxv[mi][hf]);
            float e1=__expf(acc[mi][ni][hf*2+1]-mxv[mi][hf]);
            acc[mi][ni][hf*2]=e0; acc[mi][ni][hf*2+1]=e1; s+=e0+e1;
        }
        s += __shfl_xor_sync(~0u,s,1);
        s += __shfl_xor_sync(~0u,s,2);
        if(qk==0) red[(wm*32+mi*16+hf*8+qr)*2+wn] = s;
    }
    __syncthreads();
#pragma unroll
    for(int mi=0;mi<2;++mi)
#pragma unroll
    for(int hf=0;hf<2;++hf){
        int r = wm*32+mi*16+hf*8+qr;
        inv[mi][hf] = 1.0f/(red[r*2]+red[r*2+1]);
    }
#pragma unroll
    for(int mi=0;mi<2;++mi)
#pragma unroll
    for(int hf=0;hf<2;++hf){
        int r = wm*32+mi*16+hf*8+qr;
#pragma unroll
        for(int ni=0;ni<16;++ni){
            int col = wn*128+ni*8+qk*2;
            uint32_t p2 = pk(__float2half(acc[mi][ni][hf*2]  *inv[mi][hf]),
                             __float2half(acc[mi][ni][hf*2+1]*inv[mi][hf]));
            *(uint32_t*)(sm + FA_OP + (uint32_t)r*528 + col*2) = p2;
        }
    }
    __syncthreads();

    float ao_acc[2][8][4];
#pragma unroll
    for(int i=0;i<2;++i)
#pragma unroll
        for(int j=0;j<8;++j)
#pragma unroll
            for(int q=0;q<4;++q) ao_acc[i][j][q]=0.0f;

    const uint32_t pa2 = (uint32_t)(wm*32+(lane&15))*528 + (uint32_t)(lane>>4)*16;
    const uint32_t vb2 = (uint32_t)(lane&15)*272 + (uint32_t)(lane>>4)*16 + (uint32_t)wn*128;
#pragma unroll 2
    for(int ks=0;ks<16;++ks){
        uint32_t ap[2][4];
#pragma unroll
        for(int mi=0;mi<2;++mi) LDM4(ap[mi], sbase + FA_OP + pa2 + mi*(16*528) + ks*32);
#pragma unroll
        for(int dq=0;dq<4;++dq){
            uint32_t bv[4];
            LDM4T(bv, sbase + FA_OV + vb2 + ks*(16*272) + dq*32);
#pragma unroll
            for(int hf=0;hf<2;++hf){
                int ni = dq*2+hf;
#pragma unroll
                for(int mi=0;mi<2;++mi) mma16816(ao_acc[mi][ni], ap[mi], bv+hf*2);
            }
        }
    }

    hlf* po = AO + (long)b*131072 + h*128;
#pragma unroll
    for(int mi=0;mi<2;++mi)
#pragma unroll
    for(int hf=0;hf<2;++hf){
        int row = m0 + wm*32+mi*16+hf*8+qr;
#pragma unroll
        for(int ni=0;ni<8;++ni){
            int d = wn*64+ni*8+qk*2;
            float v0=fmaxf(ao_acc[mi][ni][hf*2],0.f), v1=fmaxf(ao_acc[mi][ni][hf*2+1],0.f);
            *(uint32_t*)(po + (long)row*512 + d) = pk(__float2half(v0), __float2half(v1));
        }
    }
}

// ---------------- fused prep ----------------
__global__ void k_prep(const float* c1w, const float* b1g, const float* b1b, const float* b1m, const float* b1v,
                       const float* qw, const float* qbv, const float* kw, const float* kbv,
                       const float* vw, const float* vbv,
                       const float* b2g, const float* b2b, const float* b2m, const float* b2v,
                       const float* c3w, const float* b3g, const float* b3b, const float* b3m, const float* b3v,
                       const float* scw, const float* scb,
                       const float* sg, const float* sb, const float* smn, const float* sv,
                       const float* rh, const float* rw,
                       hlf* w1, hlf* wqkv, hlf* w3, hlf* wsc, hlf* pos){
    int blk = blockIdx.x, t = threadIdx.x;
    if(blk < 2048){
        int i = blk*256+t;
        int o = i>>10;
        w1[i] = __float2half(c1w[i] * (b1g[o]*rsqrtf(b1v[o]+EPSBN)));
    } else if(blk < 3072){
        int i = (blk-2048)*256+t;
        wqkv[i] = __float2half(qw[i]);
    } else if(blk < 4096){
        int i = (blk-3072)*256+t;
        wqkv[262144+i] = __float2half(kw[i]);
    } else if(blk < 5120){
        int i = (blk-4096)*256+t;
        int o = i>>9;
        wqkv[524288+i] = __float2half(vw[i] * (b2g[o]*rsqrtf(b2v[o]+EPSBN)));
    } else if(blk < 9216){
        int i = (blk-5120)*256+t;
        int o = i>>9;
        w3[i] = __float2half(c3w[i] * (b3g[o]*rsqrtf(b3v[o]+EPSBN)));
    } else if(blk < 17408){
        int i = (blk-9216)*256+t;
        int o = i>>10;
        wsc[i] = __float2half(scw[i] * (sg[o]*rsqrtf(sv[o]+EPSBN)));
    } else if(blk < 17920){
        int i = (blk-17408)*256+t;
        int hd = ((i>>15)<<7) + (i&127), n = (i>>7)&255;
        pos[i] = __float2half(rh[hd*16+(n&15)] + rw[hd*16+(n>>4)]);
    } else {
        int i = (blk-17920)*256+t;
        if(i<P_){
            float s1=b1g[i]*rsqrtf(b1v[i]+EPSBN); d_t1[i]=b1b[i]-b1m[i]*s1;
            float s2=b2g[i]*rsqrtf(b2v[i]+EPSBN);
            d_qkvb[i]=qbv[i];
            d_qkvb[i+512]=kbv[i];
            d_qkvb[i+1024]=fmaf(vbv[i],s2,b2b[i]-b2m[i]*s2);
        }
        if(i<COUT){
            float s3=b3g[i]*rsqrtf(b3v[i]+EPSBN);
            float ss=sg[i]*rsqrtf(sv[i]+EPSBN);
            d_tfin[i]=(b3b[i]-b3m[i]*s3) + fmaf(scb[i]-smn[i],ss,sb[i]);
        }
    }
}
__global__ void k_xt(const float* __restrict__ x, hlf* __restrict__ o){
    __shared__ float t[32][33];
    int c0=blockIdx.x*32, nn0=blockIdx.y*32, b=blockIdx.z, tx=threadIdx.x, ty=threadIdx.y;
#pragma unroll
    for(int i=0;i<4;++i) t[ty+i*8][tx] = x[((long)b*1024 + c0+ty+i*8)*256 + nn0+tx];
    __syncthreads();
    hlf* ob = o + (long)b*262144;
#pragma unroll
    for(int i=0;i<4;++i)
        ob[(long)(nn0+ty+i*8)*1024 + c0+tx] = __float2half(t[tx][ty+i*8]);
}

// ---------------- launch ----------------
extern "C" void kernel_launch(void* const* d_in, const int* in_sizes, int n_in,
                              void* d_out, int out_size) {
    const float *x=(const float*)d_in[0], *c1w=(const float*)d_in[1];
    const float *b1g=(const float*)d_in[2],*b1b=(const float*)d_in[3],*b1m=(const float*)d_in[4],*b1v=(const float*)d_in[5];
    const float *qw=(const float*)d_in[6],*qbv=(const float*)d_in[7],*kw=(const float*)d_in[8],*kbv=(const float*)d_in[9];
    const float *vw=(const float*)d_in[10],*vbv=(const float*)d_in[11],*rh=(const float*)d_in[12],*rwv=(const float*)d_in[13];
    const float *b2g=(const float*)d_in[14],*b2b=(const float*)d_in[15],*b2m=(const float*)d_in[16],*b2v=(const float*)d_in[17];
    const float *c3w=(const float*)d_in[18];
    const float *b3g=(const float*)d_in[19],*b3b=(const float*)d_in[20],*b3m=(const float*)d_in[21],*b3v=(const float*)d_in[22];
    const float *scw=(const float*)d_in[23],*scb=(const float*)d_in[24];
    const float *sg=(const float*)d_in[25],*sb=(const float*)d_in[26],*smn=(const float*)d_in[27],*sv=(const float*)d_in[28];

    hlf *xt,*w1,*wqkv,*w3,*wsc,*o1,*qkv,*ao,*pos;
    float *t1,*tf,*qkvb;
    cudaGetSymbolAddress((void**)&xt, g_xt);    cudaGetSymbolAddress((void**)&w1, g_w1);
    cudaGetSymbolAddress((void**)&wqkv,g_wqkv); cudaGetSymbolAddress((void**)&w3, g_w3);
    cudaGetSymbolAddress((void**)&wsc,g_wsc);   cudaGetSymbolAddress((void**)&o1, g_o1);
    cudaGetSymbolAddress((void**)&qkv,g_qkv);   cudaGetSymbolAddress((void**)&ao, g_ao);
    cudaGetSymbolAddress((void**)&pos,g_pos);
    cudaGetSymbolAddress((void**)&t1, d_t1);    cudaGetSymbolAddress((void**)&tf, d_tfin);
    cudaGetSymbolAddress((void**)&qkvb, d_qkvb);

    cudaFuncSetAttribute(tc<false,true ,false,true >, cudaFuncAttributeMaxDynamicSharedMemorySize, SMEMSZ);
    cudaFuncSetAttribute(tc<false,false,false,true >, cudaFuncAttributeMaxDynamicSharedMemorySize, SMEMSZ);
    cudaFuncSetAttribute(tc<true ,true ,true ,false>, cudaFuncAttributeMaxDynamicSharedMemorySize, SMEMSZ);
    cudaFuncSetAttribute(fattn, cudaFuncAttributeMaxDynamicSharedMemorySize, FA_SMEM);

    // prep (2 launches)
    k_prep<<<17928,256>>>(c1w,b1g,b1b,b1m,b1v, qw,qbv,kw,kbv, vw,vbv,
                          b2g,b2b,b2m,b2v, c3w,b3g,b3b,b3m,b3v, scw,scb,
                          sg,sb,smn,sv, rh,rwv, w1,wqkv,w3,wsc,pos);
    k_xt<<<dim3(32,8,64),dim3(32,8)>>>(x, xt);

    // 1) out1[b][n][p] = xT·w1 + t1[col], ReLU
    tc<false,true,false,true><<<dim3(4,4,64),128,SMEMSZ>>>(
        xt,262144,0,1,1024,1024,  w1,0,0,1,1024,
        nullptr,0,0,1,0,0, nullptr,0,0,1,0,
        o1,131072,0,1,512, t1);
    // 2) qkv[b][n][0..1535] = o1·[wq;wk;wv'] + qkvb[col]
    tc<false,false,false,true><<<dim3(12,4,64),128,SMEMSZ>>>(
        o1,131072,0,1,512,512,  wqkv,0,0,1,512,
        nullptr,0,0,1,0,0, nullptr,0,0,1,0,
        qkv,393216,0,1,1536, qkvb);
    // 3-5) fused attention
    fattn<<<dim3(2,256),256,FA_SMEM>>>(qkv, pos, ao);
    // 6) out[b][cout][n] = w3·attout + wsc·xT + tfin[row], ReLU (two-phase)
    tc<true,true,true,false><<<dim3(2,32,64),128,SMEMSZ>>>(
        w3,0,0,1,512,512,  ao,131072,0,1,512,
        wsc,0,0,1,1024,1024,  xt,262144,0,1,1024,
        d_out,524288,0,1,256, tf);
}